// round 14
// baseline (speedup 1.0000x reference)
#include <cuda_runtime.h>
#include <cuda_fp16.h>
#include <mma.h>
#include <cstdint>

using namespace nvcuda;

#define DIM_IO   1024
#define NHOST    4096
#define NGUEST   8192

// -------- scratch (device globals: allocation-free) --------
__device__ __half g_fh  [(size_t)NHOST  * DIM_IO];
__device__ __half g_fg  [(size_t)NGUEST * DIM_IO];
__device__ __half g_QwT [(size_t)DIM_IO * DIM_IO];
__device__ __half g_KwT [(size_t)DIM_IO * DIM_IO];
__device__ __half g_VwT [(size_t)DIM_IO * DIM_IO];
__device__ __half g_qh  [(size_t)NHOST  * DIM_IO];   // query, pre-scaled 1/32
__device__ __half g_kh  [(size_t)NGUEST * DIM_IO];
__device__ __half g_vth [(size_t)DIM_IO * NGUEST];   // value^T
__device__ __half g_P   [(size_t)NHOST  * NGUEST];   // P' = exp(logits), fp16
__device__ float  g_inv [NHOST];                     // 1 / row_sum(P')

// ============================================================
// helpers
// ============================================================
__device__ __forceinline__ void cp_async16(void* dst_smem, const void* src) {
    uint32_t a;
    asm("{ .reg .u64 t; cvta.to.shared.u64 t, %1; cvt.u32.u64 %0, t; }" : "=r"(a) : "l"(dst_smem));
    asm volatile("cp.async.cg.shared.global [%0], [%1], 16;" :: "r"(a), "l"(src) : "memory");
}
__device__ __forceinline__ void cp_commit() { asm volatile("cp.async.commit_group;" ::: "memory"); }
template <int N> __device__ __forceinline__ void cp_wait() {
    asm volatile("cp.async.wait_group %0;" :: "n"(N) : "memory");
}

// ============================================================
// fp16 WMMA GEMM: C[M,N] = alpha * A[M,K] @ B^T  (A:[M,K], B:[N,K])
// BM=128, BN=128, BK=64. 4 warps, warp tile 64x64. 3-stage cp.async.
// EXP: apply exp() in epilogue (logits -> P' fusion).
// ============================================================
#define BM 128
#define BN 128
#define BKG 64
#define LDT 72
#define STAGE_HALFS (2 * BM * LDT)
#define NSTAGES 3
#define GEMM_SMEM_BYTES (NSTAGES * STAGE_HALFS * 2)   // 110592

template <typename OutT, bool EXP>
__global__ void __launch_bounds__(128, 2)
gemm_h(const __half* __restrict__ A, const __half* __restrict__ B,
       OutT* __restrict__ C, int M, int N, int K, float alpha)
{
    extern __shared__ __align__(16) __half smem[];

    const int tid = threadIdx.x;
    const int wid = tid >> 5;
    const int wm  = wid >> 1;
    const int wn  = wid & 1;
    const int bm0 = blockIdx.y * BM;
    const int bn0 = blockIdx.x * BN;
    const int niter = K / BKG;

    using FragA  = wmma::fragment<wmma::matrix_a, 16, 16, 16, __half, wmma::row_major>;
    using FragB  = wmma::fragment<wmma::matrix_b, 16, 16, 16, __half, wmma::col_major>;
    using FragC  = wmma::fragment<wmma::accumulator, 16, 16, 16, float>;
    using FragCH = wmma::fragment<wmma::accumulator, 16, 16, 16, __half>;

    FragC acc[4][4];
    #pragma unroll
    for (int i = 0; i < 4; i++)
        #pragma unroll
        for (int j = 0; j < 4; j++)
            wmma::fill_fragment(acc[i][j], 0.0f);

    auto load_stage = [&](int s, int kit) {
        __half* As = smem + s * STAGE_HALFS;
        __half* Bs = As + BM * LDT;
        const int k0 = kit * BKG;
        #pragma unroll
        for (int t = 0; t < 8; t++) {
            int idx = tid + t * 128;
            int r = idx >> 3;
            int c = (idx & 7) << 3;
            cp_async16(As + r * LDT + c, A + (size_t)(bm0 + r) * K + k0 + c);
        }
        #pragma unroll
        for (int t = 0; t < 8; t++) {
            int idx = tid + t * 128;
            int r = idx >> 3;
            int c = (idx & 7) << 3;
            cp_async16(Bs + r * LDT + c, B + (size_t)(bn0 + r) * K + k0 + c);
        }
        cp_commit();
    };

    load_stage(0, 0);
    if (niter > 1) load_stage(1, 1);

    for (int i = 0; i < niter; i++) {
        if (i + 1 < niter) cp_wait<1>(); else cp_wait<0>();
        __syncthreads();

        if (i + 2 < niter) load_stage((i + 2) % NSTAGES, i + 2);

        const __half* As = smem + (i % NSTAGES) * STAGE_HALFS;
        const __half* Bs = As + BM * LDT;

        #pragma unroll
        for (int kk = 0; kk < BKG; kk += 16) {
            FragA af[4];
            FragB bf[4];
            #pragma unroll
            for (int x = 0; x < 4; x++)
                wmma::load_matrix_sync(af[x], As + (wm * 64 + x * 16) * LDT + kk, LDT);
            #pragma unroll
            for (int j = 0; j < 4; j++)
                wmma::load_matrix_sync(bf[j], Bs + (wn * 64 + j * 16) * LDT + kk, LDT);
            #pragma unroll
            for (int x = 0; x < 4; x++)
                #pragma unroll
                for (int j = 0; j < 4; j++)
                    wmma::mma_sync(acc[x][j], af[x], bf[j], acc[x][j]);
        }
    }

    __syncthreads();

    #pragma unroll
    for (int x = 0; x < 4; x++) {
        #pragma unroll
        for (int j = 0; j < 4; j++) {
            int row = bm0 + wm * 64 + x * 16;
            int col = bn0 + wn * 64 + j * 16;
            if constexpr (sizeof(OutT) == 2) {
                FragCH h;
                #pragma unroll
                for (int e = 0; e < acc[x][j].num_elements; e++) {
                    float v = acc[x][j].x[e] * alpha;
                    if constexpr (EXP) v = __expf(v);
                    h.x[e] = __float2half_rn(v);
                }
                wmma::store_matrix_sync((__half*)&C[(size_t)row * N + col], h, N, wmma::mem_row_major);
            } else {
                #pragma unroll
                for (int e = 0; e < acc[x][j].num_elements; e++)
                    acc[x][j].x[e] *= alpha;
                wmma::store_matrix_sync((float*)&C[(size_t)row * N + col], acc[x][j], N, wmma::mem_row_major);
            }
        }
    }
}

// ============================================================
// fp32 -> fp16 convert with scale
// ============================================================
__global__ void __launch_bounds__(256)
f32_to_f16(const float4* __restrict__ in, __half2* __restrict__ out, int n4, float s)
{
    int i = blockIdx.x * 256 + threadIdx.x;
    if (i < n4) {
        float4 v = in[i];
        out[2 * i]     = __floats2half2_rn(v.x * s, v.y * s);
        out[2 * i + 1] = __floats2half2_rn(v.z * s, v.w * s);
    }
}

// ============================================================
// weight transpose (1024x1024) fp32 -> fp16
// ============================================================
__global__ void __launch_bounds__(256)
transpose_h(const float* __restrict__ in, __half* __restrict__ out)
{
    __shared__ float t[32][33];
    int x = blockIdx.x * 32 + threadIdx.x;
    int y = blockIdx.y * 32 + threadIdx.y;
    #pragma unroll
    for (int j = 0; j < 32; j += 8)
        t[threadIdx.y + j][threadIdx.x] = in[(size_t)(y + j) * DIM_IO + x];
    __syncthreads();
    x = blockIdx.y * 32 + threadIdx.x;
    y = blockIdx.x * 32 + threadIdx.y;
    #pragma unroll
    for (int j = 0; j < 32; j += 8)
        out[(size_t)(y + j) * DIM_IO + x] = __float2half_rn(t[threadIdx.x][threadIdx.y + j]);
}

// ============================================================
// row sums of P' (fp16) -> inv_sum (fp32). One block per row.
// ============================================================
__global__ void __launch_bounds__(256)
row_sum_inv(const __half* __restrict__ P, float* __restrict__ inv, int Ncols)
{
    __shared__ float reds[8];
    const int tid = threadIdx.x;
    const __half2* prow = (const __half2*)(P + (size_t)blockIdx.x * Ncols);
    const int n2 = Ncols / 2;

    float lsum = 0.0f;
    for (int i = tid; i < n2; i += 256) {
        float2 v = __half22float2(prow[i]);
        lsum += v.x + v.y;
    }
    #pragma unroll
    for (int o = 16; o; o >>= 1)
        lsum += __shfl_xor_sync(0xffffffffu, lsum, o);
    if ((tid & 31) == 0) reds[tid >> 5] = lsum;
    __syncthreads();
    if (tid == 0) {
        float s = reds[0];
        #pragma unroll
        for (int i = 1; i < 8; i++) s += reds[i];
        inv[blockIdx.x] = 1.0f / s;
    }
}

// ============================================================
// scale rows of out (fp32 [NHOST, DIM_IO]) by inv_sum[row]
// ============================================================
__global__ void __launch_bounds__(256)
scale_rows(float4* __restrict__ out, const float* __restrict__ inv)
{
    int i = blockIdx.x * 256 + threadIdx.x;       // float4 index
    int row = i >> 8;                              // 256 float4 per row
    float s = inv[row];
    float4 v = out[i];
    v.x *= s; v.y *= s; v.z *= s; v.w *= s;
    out[i] = v;
}

// ============================================================
// one-time host-side stream/event setup (no device memory involved)
// ============================================================
struct Aux {
    cudaStream_t s1, s2;
    cudaEvent_t  e_root, e_kwt, e_h1, e_h2, e_k, e_v;
    Aux() {
        cudaStreamCreateWithFlags(&s1, cudaStreamNonBlocking);
        cudaStreamCreateWithFlags(&s2, cudaStreamNonBlocking);
        cudaEventCreateWithFlags(&e_root, cudaEventDisableTiming);
        cudaEventCreateWithFlags(&e_kwt,  cudaEventDisableTiming);
        cudaEventCreateWithFlags(&e_h1,   cudaEventDisableTiming);
        cudaEventCreateWithFlags(&e_h2,   cudaEventDisableTiming);
        cudaEventCreateWithFlags(&e_k,    cudaEventDisableTiming);
        cudaEventCreateWithFlags(&e_v,    cudaEventDisableTiming);
    }
};

// ============================================================
// launch
// ============================================================
extern "C" void kernel_launch(void* const* d_in, const int* in_sizes, int n_in,
                              void* d_out, int out_size)
{
    const float* fh = (const float*)d_in[0];
    const float* fg = (const float*)d_in[1];
    const float* Qw = (const float*)d_in[2];
    const float* Kw = (const float*)d_in[3];
    const float* Vw = (const float*)d_in[4];
    float* out = (float*)d_out;

    void *p;
    cudaGetSymbolAddress(&p, g_fh);  __half* hfh  = (__half*)p;
    cudaGetSymbolAddress(&p, g_fg);  __half* hfg  = (__half*)p;
    cudaGetSymbolAddress(&p, g_QwT); __half* hQwT = (__half*)p;
    cudaGetSymbolAddress(&p, g_KwT); __half* hKwT = (__half*)p;
    cudaGetSymbolAddress(&p, g_VwT); __half* hVwT = (__half*)p;
    cudaGetSymbolAddress(&p, g_qh);  __half* hq   = (__half*)p;
    cudaGetSymbolAddress(&p, g_kh);  __half* hk   = (__half*)p;
    cudaGetSymbolAddress(&p, g_vth); __half* hvt  = (__half*)p;
    cudaGetSymbolAddress(&p, g_P);   __half* hP   = (__half*)p;
    cudaGetSymbolAddress(&p, g_inv); float*  dinv = (float*)p;

    cudaFuncSetAttribute((const void*)gemm_h<float,  false>, cudaFuncAttributeMaxDynamicSharedMemorySize, GEMM_SMEM_BYTES);
    cudaFuncSetAttribute((const void*)gemm_h<__half, false>, cudaFuncAttributeMaxDynamicSharedMemorySize, GEMM_SMEM_BYTES);
    cudaFuncSetAttribute((const void*)gemm_h<__half, true>,  cudaFuncAttributeMaxDynamicSharedMemorySize, GEMM_SMEM_BYTES);

    static Aux ax;

    const float scale = 1.0f / 32.0f;
    dim3 tb(32, 8), tg(32, 32);

    const int FG_HALF4 = NGUEST * DIM_IO / 4 / 2;     // float4 per fg half
    const size_t FG_HALF_EL = (size_t)NGUEST * DIM_IO / 2;

    // ---- fork ----
    cudaEventRecord(ax.e_root, 0);
    cudaStreamWaitEvent(ax.s1, ax.e_root, 0);
    cudaStreamWaitEvent(ax.s2, ax.e_root, 0);

    // s1: fg convert, first half
    f32_to_f16<<<FG_HALF4 / 256, 256, 0, ax.s1>>>(
        (const float4*)fg, (__half2*)hfg, FG_HALF4, 1.0f);
    cudaEventRecord(ax.e_h1, ax.s1);

    // s2: fg convert, second half
    f32_to_f16<<<FG_HALF4 / 256, 256, 0, ax.s2>>>(
        (const float4*)(fg + FG_HALF_EL), (__half2*)(hfg + FG_HALF_EL), FG_HALF4, 1.0f);
    cudaEventRecord(ax.e_h2, ax.s2);

    // s0: KwT (off K-path now), fh convert, QwT, Q-proj
    transpose_h<<<tg, tb, 0, 0>>>(Kw, hKwT);
    cudaEventRecord(ax.e_kwt, 0);
    f32_to_f16<<<NHOST * DIM_IO / 4 / 256, 256, 0, 0>>>(
        (const float4*)fh, (__half2*)hfh, NHOST * DIM_IO / 4, 1.0f);
    transpose_h<<<tg, tb, 0, 0>>>(Qw, hQwT);
    gemm_h<__half, false><<<dim3(DIM_IO / BN, NHOST / BM), 128, GEMM_SMEM_BYTES, 0>>>(
        hfh, hQwT, hq, NHOST, DIM_IO, DIM_IO, scale);

    // s1: K-proj (needs both fg halves + KwT)
    cudaStreamWaitEvent(ax.s1, ax.e_h2, 0);
    cudaStreamWaitEvent(ax.s1, ax.e_kwt, 0);
    gemm_h<__half, false><<<dim3(DIM_IO / BN, NGUEST / BM), 128, GEMM_SMEM_BYTES, ax.s1>>>(
        hfg, hKwT, hk, NGUEST, DIM_IO, DIM_IO, 1.0f);
    cudaEventRecord(ax.e_k, ax.s1);

    // s2: VwT, V-proj (needs both fg halves) — overlaps logits on s0
    cudaStreamWaitEvent(ax.s2, ax.e_h1, 0);
    transpose_h<<<tg, tb, 0, ax.s2>>>(Vw, hVwT);
    gemm_h<__half, false><<<dim3(NGUEST / BN, DIM_IO / BM), 128, GEMM_SMEM_BYTES, ax.s2>>>(
        hVwT, hfg, hvt, DIM_IO, NGUEST, DIM_IO, 1.0f);
    cudaEventRecord(ax.e_v, ax.s2);

    // s0: P' = exp(q_scaled @ k^T), fp16, fused exp epilogue
    cudaStreamWaitEvent(0, ax.e_k, 0);
    gemm_h<__half, true><<<dim3(NGUEST / BN, NHOST / BM), 128, GEMM_SMEM_BYTES, 0>>>(
        hq, hk, hP, NHOST, NGUEST, DIM_IO, 1.0f);

    // s0: inverse row sums of P' (serial — R13 showed overlap with PV regresses)
    row_sum_inv<<<NHOST, 256, 0, 0>>>(hP, dinv, NGUEST);

    // s0: out = P' @ value (unnormalized)
    cudaStreamWaitEvent(0, ax.e_v, 0);
    gemm_h<float, false><<<dim3(DIM_IO / BN, NHOST / BM), 128, GEMM_SMEM_BYTES, 0>>>(
        hP, hvt, out, NHOST, DIM_IO, NGUEST, 1.0f);

    // s0: normalize rows
    scale_rows<<<NHOST * DIM_IO / 4 / 256, 256, 0, 0>>>((float4*)out, dinv);
}

// round 15
// speedup vs baseline: 1.0687x; 1.0687x over previous
#include <cuda_runtime.h>
#include <cuda_fp16.h>
#include <mma.h>
#include <cstdint>

using namespace nvcuda;

#define DIM_IO   1024
#define NHOST    4096
#define NGUEST   8192

// -------- scratch (device globals: allocation-free) --------
__device__ __half g_fh  [(size_t)NHOST  * DIM_IO];
__device__ __half g_fg  [(size_t)NGUEST * DIM_IO];
__device__ __half g_Qwh [(size_t)DIM_IO * DIM_IO];   // fp16 Qw (row-major, K-major in out-dim)
__device__ __half g_Kwh [(size_t)DIM_IO * DIM_IO];   // fp16 Kw
__device__ __half g_VwT [(size_t)DIM_IO * DIM_IO];
__device__ __half g_Wt  [(size_t)DIM_IO * DIM_IO];   // Wt[j,i] = sum_o Kw[j,o] Qw[i,o]
__device__ __half g_qh  [(size_t)NHOST  * DIM_IO];   // Q'' = fh @ W, pre-scaled 1/32
__device__ __half g_vth [(size_t)DIM_IO * NGUEST];   // value^T
__device__ __half g_P   [(size_t)NHOST  * NGUEST];   // P' = exp(logits), fp16
__device__ float  g_inv [NHOST];                     // 1 / row_sum(P')

// ============================================================
// helpers
// ============================================================
__device__ __forceinline__ void cp_async16(void* dst_smem, const void* src) {
    uint32_t a;
    asm("{ .reg .u64 t; cvta.to.shared.u64 t, %1; cvt.u32.u64 %0, t; }" : "=r"(a) : "l"(dst_smem));
    asm volatile("cp.async.cg.shared.global [%0], [%1], 16;" :: "r"(a), "l"(src) : "memory");
}
__device__ __forceinline__ void cp_commit() { asm volatile("cp.async.commit_group;" ::: "memory"); }
template <int N> __device__ __forceinline__ void cp_wait() {
    asm volatile("cp.async.wait_group %0;" :: "n"(N) : "memory");
}

// ============================================================
// fp16 WMMA GEMM: C[M,N] = alpha * A[M,K] @ B^T  (A:[M,K], B:[N,K])
// BM=128, BN=128, BK=64. 4 warps, warp tile 64x64. 3-stage cp.async.
// EXP: apply exp() in epilogue (logits -> P' fusion).
// ============================================================
#define BM 128
#define BN 128
#define BKG 64
#define LDT 72
#define STAGE_HALFS (2 * BM * LDT)
#define NSTAGES 3
#define GEMM_SMEM_BYTES (NSTAGES * STAGE_HALFS * 2)   // 110592

template <typename OutT, bool EXP>
__global__ void __launch_bounds__(128, 2)
gemm_h(const __half* __restrict__ A, const __half* __restrict__ B,
       OutT* __restrict__ C, int M, int N, int K, float alpha)
{
    extern __shared__ __align__(16) __half smem[];

    const int tid = threadIdx.x;
    const int wid = tid >> 5;
    const int wm  = wid >> 1;
    const int wn  = wid & 1;
    const int bm0 = blockIdx.y * BM;
    const int bn0 = blockIdx.x * BN;
    const int niter = K / BKG;

    using FragA  = wmma::fragment<wmma::matrix_a, 16, 16, 16, __half, wmma::row_major>;
    using FragB  = wmma::fragment<wmma::matrix_b, 16, 16, 16, __half, wmma::col_major>;
    using FragC  = wmma::fragment<wmma::accumulator, 16, 16, 16, float>;
    using FragCH = wmma::fragment<wmma::accumulator, 16, 16, 16, __half>;

    FragC acc[4][4];
    #pragma unroll
    for (int i = 0; i < 4; i++)
        #pragma unroll
        for (int j = 0; j < 4; j++)
            wmma::fill_fragment(acc[i][j], 0.0f);

    auto load_stage = [&](int s, int kit) {
        __half* As = smem + s * STAGE_HALFS;
        __half* Bs = As + BM * LDT;
        const int k0 = kit * BKG;
        #pragma unroll
        for (int t = 0; t < 8; t++) {
            int idx = tid + t * 128;
            int r = idx >> 3;
            int c = (idx & 7) << 3;
            cp_async16(As + r * LDT + c, A + (size_t)(bm0 + r) * K + k0 + c);
        }
        #pragma unroll
        for (int t = 0; t < 8; t++) {
            int idx = tid + t * 128;
            int r = idx >> 3;
            int c = (idx & 7) << 3;
            cp_async16(Bs + r * LDT + c, B + (size_t)(bn0 + r) * K + k0 + c);
        }
        cp_commit();
    };

    load_stage(0, 0);
    if (niter > 1) load_stage(1, 1);

    for (int i = 0; i < niter; i++) {
        if (i + 1 < niter) cp_wait<1>(); else cp_wait<0>();
        __syncthreads();

        if (i + 2 < niter) load_stage((i + 2) % NSTAGES, i + 2);

        const __half* As = smem + (i % NSTAGES) * STAGE_HALFS;
        const __half* Bs = As + BM * LDT;

        #pragma unroll
        for (int kk = 0; kk < BKG; kk += 16) {
            FragA af[4];
            FragB bf[4];
            #pragma unroll
            for (int x = 0; x < 4; x++)
                wmma::load_matrix_sync(af[x], As + (wm * 64 + x * 16) * LDT + kk, LDT);
            #pragma unroll
            for (int j = 0; j < 4; j++)
                wmma::load_matrix_sync(bf[j], Bs + (wn * 64 + j * 16) * LDT + kk, LDT);
            #pragma unroll
            for (int x = 0; x < 4; x++)
                #pragma unroll
                for (int j = 0; j < 4; j++)
                    wmma::mma_sync(acc[x][j], af[x], bf[j], acc[x][j]);
        }
    }

    __syncthreads();

    #pragma unroll
    for (int x = 0; x < 4; x++) {
        #pragma unroll
        for (int j = 0; j < 4; j++) {
            int row = bm0 + wm * 64 + x * 16;
            int col = bn0 + wn * 64 + j * 16;
            if constexpr (sizeof(OutT) == 2) {
                FragCH h;
                #pragma unroll
                for (int e = 0; e < acc[x][j].num_elements; e++) {
                    float v = acc[x][j].x[e] * alpha;
                    if constexpr (EXP) v = __expf(v);
                    h.x[e] = __float2half_rn(v);
                }
                wmma::store_matrix_sync((__half*)&C[(size_t)row * N + col], h, N, wmma::mem_row_major);
            } else {
                #pragma unroll
                for (int e = 0; e < acc[x][j].num_elements; e++)
                    acc[x][j].x[e] *= alpha;
                wmma::store_matrix_sync((float*)&C[(size_t)row * N + col], acc[x][j], N, wmma::mem_row_major);
            }
        }
    }
}

// ============================================================
// fp32 -> fp16 convert with scale
// ============================================================
__global__ void __launch_bounds__(256)
f32_to_f16(const float4* __restrict__ in, __half2* __restrict__ out, int n4, float s)
{
    int i = blockIdx.x * 256 + threadIdx.x;
    if (i < n4) {
        float4 v = in[i];
        out[2 * i]     = __floats2half2_rn(v.x * s, v.y * s);
        out[2 * i + 1] = __floats2half2_rn(v.z * s, v.w * s);
    }
}

// ============================================================
// weight transpose (1024x1024) fp32 -> fp16  (only Vw needs it now)
// ============================================================
__global__ void __launch_bounds__(256)
transpose_h(const float* __restrict__ in, __half* __restrict__ out)
{
    __shared__ float t[32][33];
    int x = blockIdx.x * 32 + threadIdx.x;
    int y = blockIdx.y * 32 + threadIdx.y;
    #pragma unroll
    for (int j = 0; j < 32; j += 8)
        t[threadIdx.y + j][threadIdx.x] = in[(size_t)(y + j) * DIM_IO + x];
    __syncthreads();
    x = blockIdx.y * 32 + threadIdx.x;
    y = blockIdx.x * 32 + threadIdx.y;
    #pragma unroll
    for (int j = 0; j < 32; j += 8)
        out[(size_t)(y + j) * DIM_IO + x] = __float2half_rn(t[threadIdx.x][threadIdx.y + j]);
}

// ============================================================
// row sums of P' (fp16) -> inv_sum (fp32). One block per row.
// ============================================================
__global__ void __launch_bounds__(256)
row_sum_inv(const __half* __restrict__ P, float* __restrict__ inv, int Ncols)
{
    __shared__ float reds[8];
    const int tid = threadIdx.x;
    const __half2* prow = (const __half2*)(P + (size_t)blockIdx.x * Ncols);
    const int n2 = Ncols / 2;

    float lsum = 0.0f;
    for (int i = tid; i < n2; i += 256) {
        float2 v = __half22float2(prow[i]);
        lsum += v.x + v.y;
    }
    #pragma unroll
    for (int o = 16; o; o >>= 1)
        lsum += __shfl_xor_sync(0xffffffffu, lsum, o);
    if ((tid & 31) == 0) reds[tid >> 5] = lsum;
    __syncthreads();
    if (tid == 0) {
        float s = reds[0];
        #pragma unroll
        for (int i = 1; i < 8; i++) s += reds[i];
        inv[blockIdx.x] = 1.0f / s;
    }
}

// ============================================================
// scale rows of out (fp32 [NHOST, DIM_IO]) by inv_sum[row]
// ============================================================
__global__ void __launch_bounds__(256)
scale_rows(float4* __restrict__ out, const float* __restrict__ inv)
{
    int i = blockIdx.x * 256 + threadIdx.x;       // float4 index
    int row = i >> 8;                              // 256 float4 per row
    float s = inv[row];
    float4 v = out[i];
    v.x *= s; v.y *= s; v.z *= s; v.w *= s;
    out[i] = v;
}

// ============================================================
// one-time host-side stream/event setup (no device memory involved)
// ============================================================
struct Aux {
    cudaStream_t s1, s2;
    cudaEvent_t  e_root, e_fg, e_v;
    Aux() {
        cudaStreamCreateWithFlags(&s1, cudaStreamNonBlocking);
        cudaStreamCreateWithFlags(&s2, cudaStreamNonBlocking);
        cudaEventCreateWithFlags(&e_root, cudaEventDisableTiming);
        cudaEventCreateWithFlags(&e_fg,   cudaEventDisableTiming);
        cudaEventCreateWithFlags(&e_v,    cudaEventDisableTiming);
    }
};

// ============================================================
// launch
// ============================================================
extern "C" void kernel_launch(void* const* d_in, const int* in_sizes, int n_in,
                              void* d_out, int out_size)
{
    const float* fh = (const float*)d_in[0];
    const float* fg = (const float*)d_in[1];
    const float* Qw = (const float*)d_in[2];
    const float* Kw = (const float*)d_in[3];
    const float* Vw = (const float*)d_in[4];
    float* out = (float*)d_out;

    void *p;
    cudaGetSymbolAddress(&p, g_fh);  __half* hfh  = (__half*)p;
    cudaGetSymbolAddress(&p, g_fg);  __half* hfg  = (__half*)p;
    cudaGetSymbolAddress(&p, g_Qwh); __half* hQw  = (__half*)p;
    cudaGetSymbolAddress(&p, g_Kwh); __half* hKw  = (__half*)p;
    cudaGetSymbolAddress(&p, g_VwT); __half* hVwT = (__half*)p;
    cudaGetSymbolAddress(&p, g_Wt);  __half* hWt  = (__half*)p;
    cudaGetSymbolAddress(&p, g_qh);  __half* hq   = (__half*)p;
    cudaGetSymbolAddress(&p, g_vth); __half* hvt  = (__half*)p;
    cudaGetSymbolAddress(&p, g_P);   __half* hP   = (__half*)p;
    cudaGetSymbolAddress(&p, g_inv); float*  dinv = (float*)p;

    cudaFuncSetAttribute((const void*)gemm_h<float,  false>, cudaFuncAttributeMaxDynamicSharedMemorySize, GEMM_SMEM_BYTES);
    cudaFuncSetAttribute((const void*)gemm_h<__half, false>, cudaFuncAttributeMaxDynamicSharedMemorySize, GEMM_SMEM_BYTES);
    cudaFuncSetAttribute((const void*)gemm_h<__half, true>,  cudaFuncAttributeMaxDynamicSharedMemorySize, GEMM_SMEM_BYTES);

    static Aux ax;

    const float scale = 1.0f / 32.0f;  // 1/sqrt(1024)
    dim3 tb(32, 8), tg(32, 32);

    // ---- fork ----
    cudaEventRecord(ax.e_root, 0);
    cudaStreamWaitEvent(ax.s1, ax.e_root, 0);
    cudaStreamWaitEvent(ax.s2, ax.e_root, 0);

    // s1: guest features -> fp16 (feeds logits-B, V-proj)
    f32_to_f16<<<NGUEST * DIM_IO / 4 / 256, 256, 0, ax.s1>>>(
        (const float4*)fg, (__half2*)hfg, NGUEST * DIM_IO / 4, 1.0f);
    cudaEventRecord(ax.e_fg, ax.s1);

    // s2: VwT, then V-proj (valT) once fg ready — overlaps s0's chain
    transpose_h<<<tg, tb, 0, ax.s2>>>(Vw, hVwT);
    cudaStreamWaitEvent(ax.s2, ax.e_fg, 0);
    gemm_h<__half, false><<<dim3(NGUEST / BN, DIM_IO / BM), 128, GEMM_SMEM_BYTES, ax.s2>>>(
        hVwT, hfg, hvt, DIM_IO, NGUEST, DIM_IO, 1.0f);
    cudaEventRecord(ax.e_v, ax.s2);

    // s0: Qw,Kw -> fp16 (no transpose needed: both K-major in out-dim)
    f32_to_f16<<<DIM_IO * DIM_IO / 4 / 256, 256, 0, 0>>>(
        (const float4*)Qw, (__half2*)hQw, DIM_IO * DIM_IO / 4, 1.0f);
    f32_to_f16<<<DIM_IO * DIM_IO / 4 / 256, 256, 0, 0>>>(
        (const float4*)Kw, (__half2*)hKw, DIM_IO * DIM_IO / 4, 1.0f);
    // s0: fh -> fp16
    f32_to_f16<<<NHOST * DIM_IO / 4 / 256, 256, 0, 0>>>(
        (const float4*)fh, (__half2*)hfh, NHOST * DIM_IO / 4, 1.0f);

    // s0: Wt[j,i] = sum_o Kw[j,o] Qw[i,o]   (= (Qw Kw^T)^T, 1024x1024)
    gemm_h<__half, false><<<dim3(DIM_IO / BN, DIM_IO / BM), 128, GEMM_SMEM_BYTES, 0>>>(
        hKw, hQw, hWt, DIM_IO, DIM_IO, DIM_IO, 1.0f);

    // s0: Q'' = scale * fh @ W  (i.e., gemm(A=fh, B=Wt))  [4096,1024] fp16
    gemm_h<__half, false><<<dim3(DIM_IO / BN, NHOST / BM), 128, GEMM_SMEM_BYTES, 0>>>(
        hfh, hWt, hq, NHOST, DIM_IO, DIM_IO, scale);

    // s0: P' = exp(Q'' @ fg^T), fp16, fused exp epilogue — NO key projection!
    cudaStreamWaitEvent(0, ax.e_fg, 0);
    gemm_h<__half, true><<<dim3(NGUEST / BN, NHOST / BM), 128, GEMM_SMEM_BYTES, 0>>>(
        hq, hfg, hP, NHOST, NGUEST, DIM_IO, 1.0f);

    // s0: inverse row sums of P' (serial — overlap with PV regresses, R13)
    row_sum_inv<<<NHOST, 256, 0, 0>>>(hP, dinv, NGUEST);

    // s0: out = P' @ value (unnormalized)
    cudaStreamWaitEvent(0, ax.e_v, 0);
    gemm_h<float, false><<<dim3(DIM_IO / BN, NHOST / BM), 128, GEMM_SMEM_BYTES, 0>>>(
        hP, hvt, out, NHOST, DIM_IO, NGUEST, 1.0f);

    // s0: normalize rows
    scale_rows<<<NHOST * DIM_IO / 4 / 256, 256, 0, 0>>>((float4*)out, dinv);
}